// round 1
// baseline (speedup 1.0000x reference)
#include <cuda_runtime.h>
#include <stdint.h>

#define T_TOK 4096
#define HDIM  1024
#define FDIM  2048
#define NEXP  8

// ---------------- scratch (__device__ globals: alloc-free) ----------------
__device__ int   g_cnt[NEXP];
__device__ int   g_tok[NEXP * T_TOK];
__device__ float g_wt [NEXP * T_TOK];
__device__ float g_h  [(size_t)NEXP * T_TOK * FDIM];   // 256 MB scratch for silu(XW1)*XW3

// ---------------- small helpers ----------------
__device__ __forceinline__ uint32_t f2tf(float f) {
    uint32_t r;
    asm("cvt.rna.tf32.f32 %0, %1;\n" : "=r"(r) : "f"(f));
    return r;
}

__device__ __forceinline__ void mma_tf32(float* d, const uint32_t* a, uint32_t b0, uint32_t b1) {
    asm volatile(
        "mma.sync.aligned.m16n8k8.row.col.f32.tf32.tf32.f32 "
        "{%0,%1,%2,%3}, {%4,%5,%6,%7}, {%8,%9}, {%0,%1,%2,%3};\n"
        : "+f"(d[0]), "+f"(d[1]), "+f"(d[2]), "+f"(d[3])
        : "r"(a[0]), "r"(a[1]), "r"(a[2]), "r"(a[3]), "r"(b0), "r"(b1));
}

#define CP_ASYNC16(dst, src) \
    asm volatile("cp.async.cg.shared.global [%0], [%1], 16;\n" :: "r"(dst), "l"(src))
#define CP_COMMIT() asm volatile("cp.async.commit_group;\n")
#define CP_WAIT0()  asm volatile("cp.async.wait_group 0;\n")

// ---------------- init ----------------
__global__ void init_counts() {
    if (threadIdx.x < NEXP) g_cnt[threadIdx.x] = 0;
}

// ---------------- router: logits, softmax, top-2, expert lists ----------------
__global__ void router_kernel(const float* __restrict__ x,
                              const float* __restrict__ gw,
                              float* __restrict__ logits_out,
                              int write_logits)
{
    int tok  = (blockIdx.x * blockDim.x + threadIdx.x) >> 5;
    int lane = threadIdx.x & 31;
    if (tok >= T_TOK) return;
    const float* xr = x + (size_t)tok * HDIM;

    float acc[NEXP];
#pragma unroll
    for (int e = 0; e < NEXP; e++) acc[e] = 0.f;
    for (int h = lane; h < HDIM; h += 32) {
        float xv = xr[h];
#pragma unroll
        for (int e = 0; e < NEXP; e++) acc[e] = fmaf(xv, gw[e * HDIM + h], acc[e]);
    }
#pragma unroll
    for (int e = 0; e < NEXP; e++) {
#pragma unroll
        for (int off = 16; off > 0; off >>= 1)
            acc[e] += __shfl_xor_sync(0xffffffffu, acc[e], off);
    }

    if (lane == 0) {
        if (write_logits) {
#pragma unroll
            for (int e = 0; e < NEXP; e++) logits_out[tok * NEXP + e] = acc[e];
        }
        float mx = acc[0];
#pragma unroll
        for (int e = 1; e < NEXP; e++) mx = fmaxf(mx, acc[e]);
        float p[NEXP], s = 0.f;
#pragma unroll
        for (int e = 0; e < NEXP; e++) { p[e] = __expf(acc[e] - mx); s += p[e]; }
        float inv = 1.f / s;
#pragma unroll
        for (int e = 0; e < NEXP; e++) p[e] *= inv;

        int i1 = 0; float m1 = p[0];
#pragma unroll
        for (int e = 1; e < NEXP; e++) if (p[e] > m1) { m1 = p[e]; i1 = e; }
        int i2 = -1; float m2 = -1.f;
#pragma unroll
        for (int e = 0; e < NEXP; e++) {
            if (e == i1) continue;
            if (p[e] > m2) { m2 = p[e]; i2 = e; }
        }

        int pos1 = atomicAdd(&g_cnt[i1], 1);
        g_tok[i1 * T_TOK + pos1] = tok;  g_wt[i1 * T_TOK + pos1] = m1;
        int pos2 = atomicAdd(&g_cnt[i2], 1);
        g_tok[i2 * T_TOK + pos2] = tok;  g_wt[i2 * T_TOK + pos2] = m2;
    }
}

// ---------------- tf32 tiled GEMM (128x128x16, cp.async double-buffered) ----
// MODE 0: g_h = silu(Xg @ W1)
// MODE 1: g_h *= (Xg @ W3)
// MODE 2: y   += wt * (g_h @ W2)   (atomicAdd)
template<int MODE, int KDIM, int NDIM>
__global__ void __launch_bounds__(256, 1)
moe_gemm(const float* __restrict__ A_x,
         const float* __restrict__ B_all,
         float* __restrict__ y_out)
{
    const int e   = blockIdx.z;
    const int cnt = g_cnt[e];
    const int m0  = blockIdx.y * 128;
    if (m0 >= cnt) return;
    const int n0  = blockIdx.x * 128;
    const float* __restrict__ B = B_all + (size_t)e * KDIM * NDIM;

    __shared__ float As[2][128][20];   // stride 20 -> conflict-free
    __shared__ float Bs[2][16][132];   // stride 132 -> conflict-free

    const int tid = threadIdx.x;

    // ---- A load mapping: 2 x 16B chunks per thread ----
    const int rA0 = tid >> 2;            // 0..63
    const int rA1 = rA0 + 64;            // 64..127
    const int cA  = (tid & 3) * 4;       // 0,4,8,12
    const float* aptr0;
    const float* aptr1;
    if (MODE < 2) {
        int mm0 = min(m0 + rA0, cnt - 1);
        int mm1 = min(m0 + rA1, cnt - 1);
        aptr0 = A_x + (size_t)g_tok[e * T_TOK + mm0] * HDIM + cA;
        aptr1 = A_x + (size_t)g_tok[e * T_TOK + mm1] * HDIM + cA;
    } else {
        aptr0 = g_h + (size_t)(e * T_TOK + m0 + rA0) * FDIM + cA;
        aptr1 = g_h + (size_t)(e * T_TOK + m0 + rA1) * FDIM + cA;
    }
    // ---- B load mapping ----
    const int rB0 = tid >> 5;            // 0..7
    const int rB1 = rB0 + 8;             // 8..15
    const int cB  = (tid & 31) * 4;      // 0..124
    const float* bptr = B + n0 + cB;

#define LOAD_TILES(buf_, k0_)                                                         \
    do {                                                                              \
        uint32_t d0 = (uint32_t)__cvta_generic_to_shared(&As[buf_][rA0][cA]);         \
        CP_ASYNC16(d0, aptr0 + (k0_));                                                \
        uint32_t d1 = (uint32_t)__cvta_generic_to_shared(&As[buf_][rA1][cA]);         \
        CP_ASYNC16(d1, aptr1 + (k0_));                                                \
        uint32_t d2 = (uint32_t)__cvta_generic_to_shared(&Bs[buf_][rB0][cB]);         \
        CP_ASYNC16(d2, bptr + (size_t)((k0_) + rB0) * NDIM);                          \
        uint32_t d3 = (uint32_t)__cvta_generic_to_shared(&Bs[buf_][rB1][cB]);         \
        CP_ASYNC16(d3, bptr + (size_t)((k0_) + rB1) * NDIM);                          \
        CP_COMMIT();                                                                  \
    } while (0)

    float acc[2][8][4];
#pragma unroll
    for (int mt = 0; mt < 2; mt++)
#pragma unroll
        for (int nt = 0; nt < 8; nt++)
#pragma unroll
            for (int i = 0; i < 4; i++) acc[mt][nt][i] = 0.f;

    const int warp = tid >> 5;
    const int lane = tid & 31;
    const int wm = warp & 3;     // 4 warps in M
    const int wn = warp >> 2;    // 2 warps in N
    const int qr = lane >> 2;    // 0..7
    const int qc = lane & 3;     // 0..3

    LOAD_TILES(0, 0);
    int buf = 0;
    const int NK = KDIM / 16;
    for (int kt = 0; kt < NK; kt++) {
        CP_WAIT0();
        __syncthreads();
        if (kt + 1 < NK) LOAD_TILES(buf ^ 1, (kt + 1) * 16);

#pragma unroll
        for (int kk = 0; kk < 16; kk += 8) {
            uint32_t a[2][4];
#pragma unroll
            for (int mt = 0; mt < 2; mt++) {
                int r = wm * 32 + mt * 16 + qr;
                a[mt][0] = f2tf(As[buf][r    ][kk + qc]);
                a[mt][1] = f2tf(As[buf][r + 8][kk + qc]);
                a[mt][2] = f2tf(As[buf][r    ][kk + qc + 4]);
                a[mt][3] = f2tf(As[buf][r + 8][kk + qc + 4]);
            }
#pragma unroll
            for (int nt = 0; nt < 8; nt++) {
                int c = wn * 64 + nt * 8 + qr;
                uint32_t b0 = f2tf(Bs[buf][kk + qc    ][c]);
                uint32_t b1 = f2tf(Bs[buf][kk + qc + 4][c]);
#pragma unroll
                for (int mt = 0; mt < 2; mt++)
                    mma_tf32(acc[mt][nt], a[mt], b0, b1);
            }
        }
        buf ^= 1;
    }

    // ---- epilogue ----
#pragma unroll
    for (int mt = 0; mt < 2; mt++) {
#pragma unroll
        for (int half = 0; half < 2; half++) {
            int rloc = wm * 32 + mt * 16 + qr + half * 8;
            int m = m0 + rloc;
            if (m >= cnt) continue;
            if (MODE == 0 || MODE == 1) {
                float* hrow = g_h + (size_t)(e * T_TOK + m) * FDIM + n0;
#pragma unroll
                for (int nt = 0; nt < 8; nt++) {
                    int c = wn * 64 + nt * 8 + qc * 2;
                    float v0 = acc[mt][nt][half * 2];
                    float v1 = acc[mt][nt][half * 2 + 1];
                    if (MODE == 0) {
                        hrow[c]     = v0 / (1.f + __expf(-v0));   // silu
                        hrow[c + 1] = v1 / (1.f + __expf(-v1));
                    } else {
                        hrow[c]     *= v0;
                        hrow[c + 1] *= v1;
                    }
                }
            } else {
                int   tokm = g_tok[e * T_TOK + m];
                float w    = g_wt [e * T_TOK + m];
                float* yrow = y_out + (size_t)tokm * HDIM + n0;
#pragma unroll
                for (int nt = 0; nt < 8; nt++) {
                    int c = wn * 64 + nt * 8 + qc * 2;
                    atomicAdd(&yrow[c],     w * acc[mt][nt][half * 2]);
                    atomicAdd(&yrow[c + 1], w * acc[mt][nt][half * 2 + 1]);
                }
            }
        }
    }
#undef LOAD_TILES
}

// ---------------- launch ----------------
extern "C" void kernel_launch(void* const* d_in, const int* in_sizes, int n_in,
                              void* d_out, int out_size)
{
    const float* x  = (const float*)d_in[0];   // [2,2048,1024]
    const float* gw = (const float*)d_in[1];   // [8,1024]
    const float* w1 = (const float*)d_in[2];   // [8,1024,2048]
    const float* w3 = (const float*)d_in[3];   // [8,1024,2048]
    const float* w2 = (const float*)d_in[4];   // [8,2048,1024]
    float* out = (float*)d_out;

    // zero y (combine target)
    cudaMemsetAsync(out, 0, (size_t)T_TOK * HDIM * sizeof(float));
    init_counts<<<1, 32>>>();

    int write_logits = (out_size >= T_TOK * HDIM + T_TOK * NEXP) ? 1 : 0;
    router_kernel<<<T_TOK / 4, 128>>>(x, gw, out + (size_t)T_TOK * HDIM, write_logits);

    dim3 g1(FDIM / 128, T_TOK / 128, NEXP);   // (16, 32, 8)
    moe_gemm<0, HDIM, FDIM><<<g1, 256>>>(x, w1, nullptr);
    moe_gemm<1, HDIM, FDIM><<<g1, 256>>>(x, w3, nullptr);

    dim3 g2(HDIM / 128, T_TOK / 128, NEXP);   // (8, 32, 8)
    moe_gemm<2, FDIM, HDIM><<<g2, 256>>>(x, w2, out);
}

// round 3
// speedup vs baseline: 1.2752x; 1.2752x over previous
#include <cuda_runtime.h>
#include <stdint.h>
#include <stddef.h>

#define T_TOK 4096
#define HDIM  1024
#define FDIM  2048
#define NEXP  8

// ---------------- scratch (__device__ globals: alloc-free) ----------------
__device__ int   g_cnt[NEXP];
__device__ int   g_tok[NEXP * T_TOK];
__device__ float g_wt [NEXP * T_TOK];
__device__ float g_h  [(size_t)NEXP * T_TOK * FDIM];   // silu(XW1)*XW3, tf32, k-permuted
__device__ float g_xr [(size_t)T_TOK * HDIM];          // x tf32-rounded, k-permuted
__device__ float g_w1t[(size_t)NEXP * FDIM * HDIM];    // w1^T [E][F][H] rounded, k-perm
__device__ float g_w3t[(size_t)NEXP * FDIM * HDIM];    // w3^T [E][F][H] rounded, k-perm
__device__ float g_w2t[(size_t)NEXP * HDIM * FDIM];    // w2^T [E][H][F] rounded, k-perm

// ---------------- helpers ----------------
__device__ __forceinline__ uint32_t smem_u32(const void* p) {
    uint32_t a;
    asm("{ .reg .u64 t; cvta.to.shared.u64 t, %1; cvt.u32.u64 %0, t; }" : "=r"(a) : "l"(p));
    return a;
}
__device__ __forceinline__ float rna_tf32(float f) {
    uint32_t r;
    asm("cvt.rna.tf32.f32 %0, %1;" : "=r"(r) : "f"(f));
    return __uint_as_float(r);
}
// logical k -> physical k within 16-blocks: phys = 4*(k%4) + k/4 (per 16)
__device__ __forceinline__ int perm16(int f) {
    return (f & ~15) | ((f & 3) << 2) | ((f >> 2) & 3);
}
// smem offset: row stride 128B (32 floats), 8 chunks of 16B, xor-swizzled
__device__ __forceinline__ uint32_t swoff(int row, int chunk) {
    return (uint32_t)(row * 128 + ((chunk ^ ((row & 1) << 2)) << 4));
}

#define CP_ASYNC16(dst, src) \
    asm volatile("cp.async.cg.shared.global [%0], [%1], 16;\n" :: "r"(dst), "l"(src))
#define CP_COMMIT() asm volatile("cp.async.commit_group;\n")
#define CP_WAIT0()  asm volatile("cp.async.wait_group 0;\n")

__device__ __forceinline__ void lds128(uint4& v, uint32_t addr) {
    asm volatile("ld.shared.v4.b32 {%0,%1,%2,%3}, [%4];"
                 : "=r"(v.x), "=r"(v.y), "=r"(v.z), "=r"(v.w) : "r"(addr));
}
__device__ __forceinline__ void mma8(float* d, uint32_t a0, uint32_t a1, uint32_t a2,
                                     uint32_t a3, uint32_t b0, uint32_t b1) {
    asm volatile(
        "mma.sync.aligned.m16n8k8.row.col.f32.tf32.tf32.f32 "
        "{%0,%1,%2,%3}, {%4,%5,%6,%7}, {%8,%9}, {%0,%1,%2,%3};\n"
        : "+f"(d[0]), "+f"(d[1]), "+f"(d[2]), "+f"(d[3])
        : "r"(a0), "r"(a1), "r"(a2), "r"(a3), "r"(b0), "r"(b1));
}

// ---------------- init ----------------
__global__ void init_counts() {
    if (threadIdx.x < NEXP) g_cnt[threadIdx.x] = 0;
}

// ---------------- router ----------------
__global__ void router_kernel(const float* __restrict__ x,
                              const float* __restrict__ gw,
                              float* __restrict__ logits_out,
                              int write_logits)
{
    int tok  = (blockIdx.x * blockDim.x + threadIdx.x) >> 5;
    int lane = threadIdx.x & 31;
    if (tok >= T_TOK) return;
    const float* xr = x + (size_t)tok * HDIM;

    float acc[NEXP];
#pragma unroll
    for (int e = 0; e < NEXP; e++) acc[e] = 0.f;
    for (int h = lane; h < HDIM; h += 32) {
        float xv = xr[h];
#pragma unroll
        for (int e = 0; e < NEXP; e++) acc[e] = fmaf(xv, gw[e * HDIM + h], acc[e]);
    }
#pragma unroll
    for (int e = 0; e < NEXP; e++) {
#pragma unroll
        for (int off = 16; off > 0; off >>= 1)
            acc[e] += __shfl_xor_sync(0xffffffffu, acc[e], off);
    }
    if (lane == 0) {
        if (write_logits) {
#pragma unroll
            for (int e = 0; e < NEXP; e++) logits_out[tok * NEXP + e] = acc[e];
        }
        float mx = acc[0];
#pragma unroll
        for (int e = 1; e < NEXP; e++) mx = fmaxf(mx, acc[e]);
        float p[NEXP], s = 0.f;
#pragma unroll
        for (int e = 0; e < NEXP; e++) { p[e] = __expf(acc[e] - mx); s += p[e]; }
        float inv = 1.f / s;
#pragma unroll
        for (int e = 0; e < NEXP; e++) p[e] *= inv;

        int i1 = 0; float m1 = p[0];
#pragma unroll
        for (int e = 1; e < NEXP; e++) if (p[e] > m1) { m1 = p[e]; i1 = e; }
        int i2 = -1; float m2 = -1.f;
#pragma unroll
        for (int e = 0; e < NEXP; e++) {
            if (e == i1) continue;
            if (p[e] > m2) { m2 = p[e]; i2 = e; }
        }
        int pos1 = atomicAdd(&g_cnt[i1], 1);
        g_tok[i1 * T_TOK + pos1] = tok;  g_wt[i1 * T_TOK + pos1] = m1;
        int pos2 = atomicAdd(&g_cnt[i2], 1);
        g_tok[i2 * T_TOK + pos2] = tok;  g_wt[i2 * T_TOK + pos2] = m2;
    }
}

// ---------------- pre-pass: round x to tf32 + k-permute ----------------
__global__ void round_x_perm(const float* __restrict__ in) {
    int i = blockIdx.x * 256 + threadIdx.x;          // T*H / 1 per thread
    float v = rna_tf32(in[i]);
    g_xr[perm16(i)] = v;                             // perm touches only low 4 bits
}

// ---------------- pre-pass: round + transpose + k-permute weights --------
// in: [E][K][N] row-major -> out: [E][N][K] (K permuted per 16), rounded
template<int W, int K, int N>
__global__ void round_transpose_kernel(const float* __restrict__ in) {
    __shared__ float t[32][33];
    float* out = (W == 0) ? g_w1t : (W == 1) ? g_w3t : g_w2t;
    const float* ie = in + (size_t)blockIdx.z * K * N;
    float* oe = out + (size_t)blockIdx.z * K * N;
    int n0 = blockIdx.x * 32, k0 = blockIdx.y * 32;
    int tx = threadIdx.x, ty = threadIdx.y;
#pragma unroll
    for (int i = 0; i < 32; i += 8)
        t[ty + i][tx] = ie[(size_t)(k0 + ty + i) * N + n0 + tx];
    __syncthreads();
    int kp = perm16(tx);
#pragma unroll
    for (int i = 0; i < 32; i += 8)
        oe[(size_t)(n0 + ty + i) * K + k0 + kp] = rna_tf32(t[tx][ty + i]);
}

// =====================================================================
// GEMM13 fused: h = silu(Xg @ W1) * (Xg @ W3)
// BM=128, BN=64, BK=32, 256 thr. Warp w: rows [rq*32,+32), cols [cf*32,+32)
// of BOTH D1 and D3 (64 acc). smem/stage: A 16K @0, B1 8K @16K, B3 8K @24K.
// =====================================================================
__global__ void __launch_bounds__(256, 2)
moe_gemm13()
{
    const int e   = blockIdx.z;
    const int cnt = g_cnt[e];
    const int m0  = blockIdx.x * 128;
    if (m0 >= cnt) return;
    const int n0  = blockIdx.y * 64;

    extern __shared__ char dsm[];
    const uint32_t sb = (smem_u32(dsm) + 127u) & ~127u;
    __shared__ const float* s_arow[128];

    const int tid  = threadIdx.x;
    const int warp = tid >> 5;
    const int lane = tid & 31;
    const int qr   = lane >> 2;
    const int qc   = lane & 3;
    const int rq   = warp & 3;
    const int cf   = warp >> 2;

    if (tid < 128) {
        int mm = min(m0 + tid, cnt - 1);
        s_arow[tid] = g_xr + (size_t)g_tok[e * T_TOK + mm] * HDIM;
    }
    __syncthreads();

    const float* b1b = g_w1t + (size_t)e * FDIM * HDIM + (size_t)n0 * HDIM;
    const float* b3b = g_w3t + (size_t)e * FDIM * HDIM + (size_t)n0 * HDIM;

    const int ch  = tid & 7;
    const int rr  = tid >> 3;       // 0..31
    // precompute per-thread src pointers + dst smem offsets
    const float* pA[4]; uint32_t dA[4];
#pragma unroll
    for (int i = 0; i < 4; i++) {
        int row = i * 32 + rr;
        pA[i] = s_arow[row] + ch * 4;
        dA[i] = sb + swoff(row, ch);
    }
    const float* pB1[2]; const float* pB3[2]; uint32_t dB[2];
#pragma unroll
    for (int i = 0; i < 2; i++) {
        int row = i * 32 + rr;      // 0..63
        pB1[i] = b1b + (size_t)row * HDIM + ch * 4;
        pB3[i] = b3b + (size_t)row * HDIM + ch * 4;
        dB[i]  = sb + swoff(row, ch);
    }

#define LOAD13(st_, k0_) do {                                             \
    uint32_t so_ = (uint32_t)(st_) * 32768u;                              \
    _Pragma("unroll")                                                     \
    for (int i_ = 0; i_ < 4; i_++)                                        \
        CP_ASYNC16(dA[i_] + so_, pA[i_] + (k0_));                         \
    _Pragma("unroll")                                                     \
    for (int i_ = 0; i_ < 2; i_++) {                                      \
        CP_ASYNC16(dB[i_] + 16384u + so_, pB1[i_] + (k0_));               \
        CP_ASYNC16(dB[i_] + 24576u + so_, pB3[i_] + (k0_));               \
    }                                                                     \
    CP_COMMIT();                                                          \
} while (0)

    float acc1[2][4][4], acc3[2][4][4];
#pragma unroll
    for (int mt = 0; mt < 2; mt++)
#pragma unroll
        for (int nt = 0; nt < 4; nt++)
#pragma unroll
            for (int i = 0; i < 4; i++) { acc1[mt][nt][i] = 0.f; acc3[mt][nt][i] = 0.f; }

    LOAD13(0, 0);
    const int NT = HDIM / 32;   // 32
    for (int t = 0; t < NT; t++) {
        const uint32_t st = (uint32_t)(t & 1) * 32768u;
        CP_WAIT0();
        __syncthreads();
        if (t + 1 < NT) LOAD13((t + 1) & 1, (t + 1) * 32);

#pragma unroll
        for (int s = 0; s < 2; s++) {
            uint4 alo[2], ahi[2];
#pragma unroll
            for (int mt = 0; mt < 2; mt++) {
                int r = rq * 32 + mt * 16 + qr;
                lds128(alo[mt], sb + st + swoff(r,     4 * s + qc));
                lds128(ahi[mt], sb + st + swoff(r + 8, 4 * s + qc));
            }
#pragma unroll
            for (int nt = 0; nt < 4; nt++) {
                int n = cf * 32 + nt * 8 + qr;
                uint4 b1v, b3v;
                lds128(b1v, sb + st + 16384u + swoff(n, 4 * s + qc));
                lds128(b3v, sb + st + 24576u + swoff(n, 4 * s + qc));
#pragma unroll
                for (int mt = 0; mt < 2; mt++) {
                    mma8(acc1[mt][nt], alo[mt].x, ahi[mt].x, alo[mt].y, ahi[mt].y, b1v.x, b1v.y);
                    mma8(acc1[mt][nt], alo[mt].z, ahi[mt].z, alo[mt].w, ahi[mt].w, b1v.z, b1v.w);
                    mma8(acc3[mt][nt], alo[mt].x, ahi[mt].x, alo[mt].y, ahi[mt].y, b3v.x, b3v.y);
                    mma8(acc3[mt][nt], alo[mt].z, ahi[mt].z, alo[mt].w, ahi[mt].w, b3v.z, b3v.w);
                }
            }
        }
    }

    // epilogue: g_h[m][perm16(f)] = rna(silu(d1)*d3)
#pragma unroll
    for (int mt = 0; mt < 2; mt++) {
#pragma unroll
        for (int h = 0; h < 2; h++) {
            int m = m0 + rq * 32 + mt * 16 + qr + 8 * h;
            if (m >= cnt) continue;
            float* hrow = g_h + ((size_t)e * T_TOK + m) * FDIM;
#pragma unroll
            for (int nt = 0; nt < 4; nt++) {
#pragma unroll
                for (int b = 0; b < 2; b++) {
                    float d1 = acc1[mt][nt][2 * h + b];
                    float d3 = acc3[mt][nt][2 * h + b];
                    float v = rna_tf32(d1 / (1.f + __expf(-d1)) * d3);
                    int f = n0 + cf * 32 + nt * 8 + qc * 2 + b;
                    hrow[perm16(f)] = v;
                }
            }
        }
    }
#undef LOAD13
}

// =====================================================================
// GEMM2: y += wt * (h @ W2).  BM=128, BN=128, BK=32, 256 thr.
// Warp w: rows [rq*32,+32), cols [cf*64,+64). smem/stage: A 16K @0, B 16K @16K.
// =====================================================================
__global__ void __launch_bounds__(256, 2)
moe_gemm2(float* __restrict__ y)
{
    const int e   = blockIdx.z;
    const int cnt = g_cnt[e];
    const int m0  = blockIdx.x * 128;
    if (m0 >= cnt) return;
    const int n0  = blockIdx.y * 128;

    extern __shared__ char dsm[];
    const uint32_t sb = (smem_u32(dsm) + 127u) & ~127u;
    __shared__ const float* s_arow[128];

    const int tid  = threadIdx.x;
    const int warp = tid >> 5;
    const int lane = tid & 31;
    const int qr   = lane >> 2;
    const int qc   = lane & 3;
    const int rq   = warp & 3;
    const int cf   = warp >> 2;

    if (tid < 128) {
        int mm = min(m0 + tid, cnt - 1);
        s_arow[tid] = g_h + ((size_t)e * T_TOK + mm) * FDIM;
    }
    __syncthreads();

    const float* bb = g_w2t + (size_t)e * HDIM * FDIM + (size_t)n0 * FDIM;

    const int ch = tid & 7;
    const int rr = tid >> 3;
    const float* pA[4]; uint32_t dA[4]; const float* pB[4]; uint32_t dB[4];
#pragma unroll
    for (int i = 0; i < 4; i++) {
        int row = i * 32 + rr;
        pA[i] = s_arow[row] + ch * 4;
        dA[i] = sb + swoff(row, ch);
        pB[i] = bb + (size_t)row * FDIM + ch * 4;
        dB[i] = sb + 16384u + swoff(row, ch);
    }

#define LOAD2(st_, k0_) do {                                              \
    uint32_t so_ = (uint32_t)(st_) * 32768u;                              \
    _Pragma("unroll")                                                     \
    for (int i_ = 0; i_ < 4; i_++) {                                      \
        CP_ASYNC16(dA[i_] + so_, pA[i_] + (k0_));                         \
        CP_ASYNC16(dB[i_] + so_, pB[i_] + (k0_));                         \
    }                                                                     \
    CP_COMMIT();                                                          \
} while (0)

    float acc[2][8][4];
#pragma unroll
    for (int mt = 0; mt < 2; mt++)
#pragma unroll
        for (int nt = 0; nt < 8; nt++)
#pragma unroll
            for (int i = 0; i < 4; i++) acc[mt][nt][i] = 0.f;

    LOAD2(0, 0);
    const int NT = FDIM / 32;   // 64
    for (int t = 0; t < NT; t++) {
        const uint32_t st = (uint32_t)(t & 1) * 32768u;
        CP_WAIT0();
        __syncthreads();
        if (t + 1 < NT) LOAD2((t + 1) & 1, (t + 1) * 32);

#pragma unroll
        for (int s = 0; s < 2; s++) {
            uint4 alo[2], ahi[2];
#pragma unroll
            for (int mt = 0; mt < 2; mt++) {
                int r = rq * 32 + mt * 16 + qr;
                lds128(alo[mt], sb + st + swoff(r,     4 * s + qc));
                lds128(ahi[mt], sb + st + swoff(r + 8, 4 * s + qc));
            }
#pragma unroll
            for (int nt = 0; nt < 8; nt++) {
                int n = cf * 64 + nt * 8 + qr;
                uint4 bv;
                lds128(bv, sb + st + 16384u + swoff(n, 4 * s + qc));
#pragma unroll
                for (int mt = 0; mt < 2; mt++) {
                    mma8(acc[mt][nt], alo[mt].x, ahi[mt].x, alo[mt].y, ahi[mt].y, bv.x, bv.y);
                    mma8(acc[mt][nt], alo[mt].z, ahi[mt].z, alo[mt].w, ahi[mt].w, bv.z, bv.w);
                }
            }
        }
    }

    // epilogue: y[tok] += wt * D (atomic combine), natural columns
#pragma unroll
    for (int mt = 0; mt < 2; mt++) {
#pragma unroll
        for (int h = 0; h < 2; h++) {
            int m = m0 + rq * 32 + mt * 16 + qr + 8 * h;
            if (m >= cnt) continue;
            float w   = g_wt [e * T_TOK + m];
            int   tok = g_tok[e * T_TOK + m];
            float* yrow = y + (size_t)tok * HDIM + n0 + cf * 64;
#pragma unroll
            for (int nt = 0; nt < 8; nt++) {
#pragma unroll
                for (int b = 0; b < 2; b++)
                    atomicAdd(yrow + nt * 8 + qc * 2 + b, w * acc[mt][nt][2 * h + b]);
            }
        }
    }
#undef LOAD2
}

// ---------------- launch ----------------
extern "C" void kernel_launch(void* const* d_in, const int* in_sizes, int n_in,
                              void* d_out, int out_size)
{
    const float* x  = (const float*)d_in[0];   // [2,2048,1024]
    const float* gw = (const float*)d_in[1];   // [8,1024]
    const float* w1 = (const float*)d_in[2];   // [8,1024,2048]
    const float* w3 = (const float*)d_in[3];   // [8,1024,2048]
    const float* w2 = (const float*)d_in[4];   // [8,2048,1024]
    float* out = (float*)d_out;

    cudaFuncSetAttribute(moe_gemm13, cudaFuncAttributeMaxDynamicSharedMemorySize, 66048);
    cudaFuncSetAttribute(moe_gemm2,  cudaFuncAttributeMaxDynamicSharedMemorySize, 66048);

    cudaMemsetAsync(out, 0, (size_t)T_TOK * HDIM * sizeof(float));
    init_counts<<<1, 32>>>();

    int write_logits = (out_size >= T_TOK * HDIM + T_TOK * NEXP) ? 1 : 0;
    router_kernel<<<T_TOK / 4, 128>>>(x, gw, out + (size_t)T_TOK * HDIM, write_logits);

    // pre-pass: tf32-round + layout transforms
    round_x_perm<<<T_TOK * HDIM / 256, 256>>>(x);
    {
        dim3 b(32, 8);
        round_transpose_kernel<0, HDIM, FDIM><<<dim3(FDIM / 32, HDIM / 32, NEXP), b>>>(w1);
        round_transpose_kernel<1, HDIM, FDIM><<<dim3(FDIM / 32, HDIM / 32, NEXP), b>>>(w3);
        round_transpose_kernel<2, FDIM, HDIM><<<dim3(HDIM / 32, FDIM / 32, NEXP), b>>>(w2);
    }

    // grid.x = M-blocks fastest (B-tile / expert A-slice L2 reuse)
    moe_gemm13<<<dim3(T_TOK / 128, FDIM / 64, NEXP), 256, 66048>>>();
    moe_gemm2 <<<dim3(T_TOK / 128, HDIM / 128, NEXP), 256, 66048>>>(out);
}